// round 2
// baseline (speedup 1.0000x reference)
#include <cuda_runtime.h>

// LIF forward: X[B=128, T=32, N=8192] fp32 -> spikes fp32.
// R2: explicit MLP. Each thread owns 2 independent float4 columns
// (grid-strided), t-loop chunked by 4 so 8 independent loads are batched
// ahead of the dependent recurrence chain. Streaming cache hints since
// every byte is touched exactly once.

static constexpr int B = 128;
static constexpr int T = 32;
static constexpr int N = 8192;
static constexpr int N4 = N / 4;            // 2048 float4 columns
static constexpr int TOTAL4 = B * N4;       // 262144 float4 lanes
static constexpr int COLS = 2;              // columns per thread
static constexpr int NTHREADS = TOTAL4 / COLS;  // 131072
static constexpr int TPB = 256;
static constexpr int TCHUNK = 4;

__device__ __forceinline__ void lif_step(float& m, const float4& x, float4& s) {
    // match reference rounding exactly: mem += (x - mem) * 0.5
    // (done componentwise below)
    (void)m; (void)x; (void)s;
}

__device__ __forceinline__ float4 step4(float4& m, const float4 x) {
    m.x = m.x + (x.x - m.x) * 0.5f;
    m.y = m.y + (x.y - m.y) * 0.5f;
    m.z = m.z + (x.z - m.z) * 0.5f;
    m.w = m.w + (x.w - m.w) * 0.5f;
    float4 s;
    s.x = (m.x > 1.0f) ? 1.0f : 0.0f;
    s.y = (m.y > 1.0f) ? 1.0f : 0.0f;
    s.z = (m.z > 1.0f) ? 1.0f : 0.0f;
    s.w = (m.w > 1.0f) ? 1.0f : 0.0f;
    if (s.x != 0.0f) m.x = 0.0f;
    if (s.y != 0.0f) m.y = 0.0f;
    if (s.z != 0.0f) m.z = 0.0f;
    if (s.w != 0.0f) m.w = 0.0f;
    return s;
}

__global__ __launch_bounds__(TPB) void lif_kernel(const float4* __restrict__ X,
                                                  float4* __restrict__ out) {
    int idx = blockIdx.x * TPB + threadIdx.x;   // 0 .. NTHREADS-1

    // column 0: idx, column 1: idx + NTHREADS (both warp-coalesced)
    int c0 = idx;
    int c1 = idx + NTHREADS;

    int b0 = c0 / N4, n0 = c0 - b0 * N4;
    int b1 = c1 / N4, n1 = c1 - b1 * N4;

    const float4* xp0 = X + (size_t)b0 * T * N4 + n0;
    const float4* xp1 = X + (size_t)b1 * T * N4 + n1;
    float4* op0 = out + (size_t)b0 * T * N4 + n0;
    float4* op1 = out + (size_t)b1 * T * N4 + n1;

    float4 m0 = make_float4(0.f, 0.f, 0.f, 0.f);
    float4 m1 = make_float4(0.f, 0.f, 0.f, 0.f);

#pragma unroll
    for (int tc = 0; tc < T; tc += TCHUNK) {
        float4 x0[TCHUNK], x1[TCHUNK];
        // 8 independent loads batched ahead of the dependent chain
#pragma unroll
        for (int j = 0; j < TCHUNK; j++) {
            x0[j] = __ldcs(&xp0[(size_t)(tc + j) * N4]);
            x1[j] = __ldcs(&xp1[(size_t)(tc + j) * N4]);
        }

        float4 s0[TCHUNK], s1[TCHUNK];
#pragma unroll
        for (int j = 0; j < TCHUNK; j++) {
            s0[j] = step4(m0, x0[j]);
            s1[j] = step4(m1, x1[j]);
        }

#pragma unroll
        for (int j = 0; j < TCHUNK; j++) {
            __stcs(&op0[(size_t)(tc + j) * N4], s0[j]);
            __stcs(&op1[(size_t)(tc + j) * N4], s1[j]);
        }
    }
}

extern "C" void kernel_launch(void* const* d_in, const int* in_sizes, int n_in,
                              void* d_out, int out_size) {
    const float4* X = (const float4*)d_in[0];
    float4* out = (float4*)d_out;
    lif_kernel<<<NTHREADS / TPB, TPB>>>(X, out);
}

// round 3
// speedup vs baseline: 1.0437x; 1.0437x over previous
#include <cuda_runtime.h>

// LIF forward: X[B=128, T=32, N=8192] fp32 -> spikes fp32.
// R3: R1 layout (1 float4 column / thread, occ ~64%) + explicit 4-deep
// load batching per t-chunk so 4 LDG.128 are in flight ahead of the
// dependent recurrence chain. Register budget kept ~40 to preserve occupancy.

static constexpr int B = 128;
static constexpr int T = 32;
static constexpr int N = 8192;
static constexpr int N4 = N / 4;          // 2048 float4 columns
static constexpr int TOTAL4 = B * N4;     // 262144 float4 lanes
static constexpr int TPB = 256;
static constexpr int TCHUNK = 4;

__device__ __forceinline__ float4 step4(float4& m, const float4 x) {
    m.x = m.x + (x.x - m.x) * 0.5f;
    m.y = m.y + (x.y - m.y) * 0.5f;
    m.z = m.z + (x.z - m.z) * 0.5f;
    m.w = m.w + (x.w - m.w) * 0.5f;
    float4 s;
    s.x = (m.x > 1.0f) ? 1.0f : 0.0f;
    s.y = (m.y > 1.0f) ? 1.0f : 0.0f;
    s.z = (m.z > 1.0f) ? 1.0f : 0.0f;
    s.w = (m.w > 1.0f) ? 1.0f : 0.0f;
    if (s.x != 0.0f) m.x = 0.0f;
    if (s.y != 0.0f) m.y = 0.0f;
    if (s.z != 0.0f) m.z = 0.0f;
    if (s.w != 0.0f) m.w = 0.0f;
    return s;
}

__global__ __launch_bounds__(TPB) void lif_kernel(const float4* __restrict__ X,
                                                  float4* __restrict__ out) {
    int idx = blockIdx.x * TPB + threadIdx.x;  // 0 .. TOTAL4-1

    int b = idx / N4;
    int n4 = idx - b * N4;

    const float4* xp = X + (size_t)b * T * N4 + n4;
    float4* op = out + (size_t)b * T * N4 + n4;

    float4 m = make_float4(0.f, 0.f, 0.f, 0.f);

#pragma unroll
    for (int tc = 0; tc < T; tc += TCHUNK) {
        float4 x[TCHUNK];
        // batch 4 independent 16B loads ahead of the dependent chain
#pragma unroll
        for (int j = 0; j < TCHUNK; j++)
            x[j] = xp[(size_t)(tc + j) * N4];

#pragma unroll
        for (int j = 0; j < TCHUNK; j++) {
            float4 s = step4(m, x[j]);
            op[(size_t)(tc + j) * N4] = s;
        }
    }
}

extern "C" void kernel_launch(void* const* d_in, const int* in_sizes, int n_in,
                              void* d_out, int out_size) {
    const float4* X = (const float4*)d_in[0];
    float4* out = (float4*)d_out;
    lif_kernel<<<TOTAL4 / TPB, TPB>>>(X, out);
}

// round 4
// speedup vs baseline: 1.0536x; 1.0095x over previous
#include <cuda_runtime.h>
#include <cstdint>

// LIF forward: X[B=128, T=32, N=8192] fp32 -> spikes fp32.
// R4: bulk-async (TMA-class) pipeline. Per CTA: 1024 columns of one batch
// row, all T=32 planes. 8-stage input ring (cp.async.bulk + mbarrier),
// 2-stage output ring (cp.async.bulk store + bulk_group). Recurrence state
// lives in registers; loads are issued 8 planes ahead at zero register cost.

static constexpr int B = 128;
static constexpr int T = 32;
static constexpr int N = 8192;
static constexpr int TILE = 1024;              // floats per CTA per t-plane
static constexpr int TILE_BYTES = TILE * 4;    // 4096 B
static constexpr int PLANE_BYTES = N * 4;      // 32768 B (stride between t)
static constexpr int TILES_PER_B = N / TILE;   // 8
static constexpr int GRID = B * TILES_PER_B;   // 1024
static constexpr int TPB = 256;                // 1 float4 per thread per plane
static constexpr int STAGES = 8;               // input ring depth
static constexpr int OUT_STAGES = 2;           // output ring depth

static constexpr int SMEM_IN = 0;
static constexpr int SMEM_OUT = SMEM_IN + STAGES * TILE_BYTES;      // 32768
static constexpr int SMEM_MBAR = SMEM_OUT + OUT_STAGES * TILE_BYTES; // 40960
static constexpr int SMEM_TOTAL = SMEM_MBAR + STAGES * 8 + 64;       // ~41 KB

__device__ __forceinline__ uint32_t smem_u32(const void* p) {
    return (uint32_t)__cvta_generic_to_shared(p);
}

__device__ __forceinline__ void mbar_init(uint32_t mbar, uint32_t count) {
    asm volatile("mbarrier.init.shared.b64 [%0], %1;" :: "r"(mbar), "r"(count) : "memory");
}

__device__ __forceinline__ void mbar_expect_tx(uint32_t mbar, uint32_t bytes) {
    asm volatile("mbarrier.arrive.expect_tx.shared.b64 _, [%0], %1;"
                 :: "r"(mbar), "r"(bytes) : "memory");
}

__device__ __forceinline__ void mbar_wait(uint32_t mbar, uint32_t parity) {
    uint32_t done;
    asm volatile(
        "{\n\t.reg .pred p;\n\t"
        "mbarrier.try_wait.parity.acquire.cta.shared::cta.b64 p, [%1], %2;\n\t"
        "selp.b32 %0, 1, 0, p;\n\t}"
        : "=r"(done) : "r"(mbar), "r"(parity) : "memory");
    if (!done) {
        asm volatile(
            "{\n\t.reg .pred P1;\n\t"
            "WAIT_LOOP_%=:\n\t"
            "mbarrier.try_wait.parity.acquire.cta.shared::cta.b64 P1, [%0], %1, 0x989680;\n\t"
            "@P1 bra.uni WAIT_DONE_%=;\n\t"
            "bra.uni WAIT_LOOP_%=;\n\t"
            "WAIT_DONE_%=:\n\t}"
            :: "r"(mbar), "r"(parity) : "memory");
    }
}

__device__ __forceinline__ void bulk_load(uint32_t dst_smem, const void* src_gmem,
                                          uint32_t bytes, uint32_t mbar) {
    asm volatile(
        "cp.async.bulk.shared::cta.global.mbarrier::complete_tx::bytes [%0], [%1], %2, [%3];"
        :: "r"(dst_smem), "l"(src_gmem), "r"(bytes), "r"(mbar) : "memory");
}

__device__ __forceinline__ void bulk_store(void* dst_gmem, uint32_t src_smem,
                                           uint32_t bytes) {
    asm volatile(
        "cp.async.bulk.global.shared::cta.bulk_group [%0], [%1], %2;"
        :: "l"(dst_gmem), "r"(src_smem), "r"(bytes) : "memory");
}

__device__ __forceinline__ float4 step4(float4& m, const float4 x) {
    m.x = m.x + (x.x - m.x) * 0.5f;
    m.y = m.y + (x.y - m.y) * 0.5f;
    m.z = m.z + (x.z - m.z) * 0.5f;
    m.w = m.w + (x.w - m.w) * 0.5f;
    float4 s;
    s.x = (m.x > 1.0f) ? 1.0f : 0.0f;
    s.y = (m.y > 1.0f) ? 1.0f : 0.0f;
    s.z = (m.z > 1.0f) ? 1.0f : 0.0f;
    s.w = (m.w > 1.0f) ? 1.0f : 0.0f;
    if (s.x != 0.0f) m.x = 0.0f;
    if (s.y != 0.0f) m.y = 0.0f;
    if (s.z != 0.0f) m.z = 0.0f;
    if (s.w != 0.0f) m.w = 0.0f;
    return s;
}

__global__ __launch_bounds__(TPB) void lif_kernel(const float* __restrict__ X,
                                                  float* __restrict__ out) {
    extern __shared__ char smem[];
    const uint32_t sbase = smem_u32(smem);
    const uint32_t in_base = sbase + SMEM_IN;
    const uint32_t out_base = sbase + SMEM_OUT;
    const uint32_t mbar_base = sbase + SMEM_MBAR;

    const int tid = threadIdx.x;
    const int cta = blockIdx.x;
    const int b = cta / TILES_PER_B;
    const int tile = cta - b * TILES_PER_B;

    const char* gin = (const char*)X + ((size_t)b * T * N + (size_t)tile * TILE) * 4;
    char* gout = (char*)out + ((size_t)b * T * N + (size_t)tile * TILE) * 4;

    if (tid == 0) {
#pragma unroll
        for (int s = 0; s < STAGES; s++) mbar_init(mbar_base + s * 8, 1);
    }
    __syncthreads();

    if (tid == 0) {
#pragma unroll
        for (int s = 0; s < STAGES; s++) {
            mbar_expect_tx(mbar_base + s * 8, TILE_BYTES);
            bulk_load(in_base + s * TILE_BYTES, gin + (size_t)s * PLANE_BYTES,
                      TILE_BYTES, mbar_base + s * 8);
        }
    }

    float4 m = make_float4(0.f, 0.f, 0.f, 0.f);
    const uint32_t lane_off = (uint32_t)tid * 16;

    for (int t = 0; t < T; t++) {
        const int s = t & (STAGES - 1);
        const uint32_t ph = (uint32_t)(t / STAGES) & 1u;
        const int o = t & (OUT_STAGES - 1);

        mbar_wait(mbar_base + s * 8, ph);

        float4 x = *reinterpret_cast<const float4*>(
            smem + SMEM_IN + s * TILE_BYTES + lane_off);
        float4 sp = step4(m, x);

        // make sure out buffer o's previous bulk store has drained
        if (tid == 0) {
            asm volatile("cp.async.bulk.wait_group.read %0;" :: "n"(OUT_STAGES - 1) : "memory");
        }
        __syncthreads();  // all read in[s]; out[o] free

        *reinterpret_cast<float4*>(smem + SMEM_OUT + o * TILE_BYTES + lane_off) = sp;
        __syncthreads();  // out[o] fully written; in[s] reusable

        if (tid == 0) {
            asm volatile("fence.proxy.async.shared::cta;" ::: "memory");
            bulk_store(gout + (size_t)t * PLANE_BYTES,
                       out_base + o * TILE_BYTES, TILE_BYTES);
            asm volatile("cp.async.bulk.commit_group;" ::: "memory");
            const int tn = t + STAGES;
            if (tn < T) {
                mbar_expect_tx(mbar_base + s * 8, TILE_BYTES);
                bulk_load(in_base + s * TILE_BYTES, gin + (size_t)tn * PLANE_BYTES,
                          TILE_BYTES, mbar_base + s * 8);
            }
        }
    }

    // drain outstanding stores before exit
    if (tid == 0) {
        asm volatile("cp.async.bulk.wait_group.read 0;" ::: "memory");
    }
}

extern "C" void kernel_launch(void* const* d_in, const int* in_sizes, int n_in,
                              void* d_out, int out_size) {
    const float* X = (const float*)d_in[0];
    float* out = (float*)d_out;
    cudaFuncSetAttribute(lif_kernel, cudaFuncAttributeMaxDynamicSharedMemorySize,
                         SMEM_TOTAL);
    lif_kernel<<<GRID, TPB, SMEM_TOTAL>>>(X, out);
}